// round 14
// baseline (speedup 1.0000x reference)
#include <cuda_runtime.h>
#include <cuda_fp16.h>
#include <cstdint>
#include <cstddef>

#define NN 2048      // nodes
#define BB 16        // batch
#define TT 256       // time/feature dim
#define K3 (3*TT)    // 768  (sim split K)

// ---------------- device scratch (no allocations allowed) ----------------
__device__ float g_xavg[TT * NN];                  // [t][n]
__device__ __half g_xa3[(size_t)NN * K3];          // [n][768] = [h, l, h]
__device__ __half g_xb3[(size_t)NN * K3];          // [n][768] = [h, h, l]
__device__ __half g_wT[TT * TT];                   // [o][t] fp16
__device__ __half g_xT[(size_t)BB * NN * TT];      // [b][n][t] fp16
__device__ unsigned char g_adj8[(size_t)NN * NN];  // directed adjacency 0/1
__device__ signed char g_nm8[(size_t)NN * NN];     // nmask 0/1 (s8)
__device__ unsigned short g_common16[(size_t)NN * NN]; // exact counts, lower-tri valid
__device__ __half g_WT[(size_t)NN * NN];           // [d][s] = fp16(Wn^T)
__device__ __half g_Y[(size_t)BB * TT * NN];       // [4096][2048] fp16(Y)
__device__ unsigned long long g_deg64[NN];         // exact integer deg sums

// ---------------- PTX helpers (sm_80-level features only) ----------------
__device__ __forceinline__ uint32_t smem_u32(const void* p) {
    uint32_t a;
    asm("{ .reg .u64 t; cvta.to.shared.u64 t, %1; cvt.u32.u64 %0, t; }"
        : "=r"(a) : "l"(p));
    return a;
}

#define CP16(dst, src) \
    asm volatile("cp.async.cg.shared.global [%0], [%1], 16;" :: "r"(dst), "l"(src))
#define CP_COMMIT() asm volatile("cp.async.commit_group;" ::: "memory")
#define CP_WAIT2()  asm volatile("cp.async.wait_group 2;" ::: "memory")

__device__ __forceinline__ void ldsm_x4(uint32_t& r0, uint32_t& r1, uint32_t& r2,
                                        uint32_t& r3, uint32_t addr) {
    asm volatile("ldmatrix.sync.aligned.m8n8.x4.shared.b16 {%0,%1,%2,%3}, [%4];"
                 : "=r"(r0), "=r"(r1), "=r"(r2), "=r"(r3) : "r"(addr));
}

__device__ __forceinline__ void mma16816(float* c, const uint32_t* a, const uint32_t* b) {
    asm volatile(
        "mma.sync.aligned.m16n8k16.row.col.f32.f16.f16.f32 "
        "{%0,%1,%2,%3}, {%4,%5,%6,%7}, {%8,%9}, {%0,%1,%2,%3};"
        : "+f"(c[0]), "+f"(c[1]), "+f"(c[2]), "+f"(c[3])
        : "r"(a[0]), "r"(a[1]), "r"(a[2]), "r"(a[3]), "r"(b[0]), "r"(b[1]));
}

// f16-accumulator mma with C=0: output = single-rounded k16 dot product.
__device__ __forceinline__ void mma16816f16(uint32_t* d, const uint32_t* a, const uint32_t* b) {
    asm volatile(
        "mma.sync.aligned.m16n8k16.row.col.f16.f16.f16.f16 "
        "{%0,%1}, {%2,%3,%4,%5}, {%6,%7}, {%8,%8};"
        : "=r"(d[0]), "=r"(d[1])
        : "r"(a[0]), "r"(a[1]), "r"(a[2]), "r"(a[3]), "r"(b[0]), "r"(b[1]), "r"(0u));
}

__device__ __forceinline__ void mma16832s8(int* c, const uint32_t* a, const uint32_t* b) {
    asm volatile(
        "mma.sync.aligned.m16n8k32.row.col.s32.s8.s8.s32 "
        "{%0,%1,%2,%3}, {%4,%5,%6,%7}, {%8,%9}, {%0,%1,%2,%3};"
        : "+r"(c[0]), "+r"(c[1]), "+r"(c[2]), "+r"(c[3])
        : "r"(a[0]), "r"(a[1]), "r"(a[2]), "r"(a[3]), "r"(b[0]), "r"(b[1]));
}

// decode 1D lower-triangle index -> (bi >= bj)
__device__ __forceinline__ void tri_decode(int idx, int& bi, int& bj) {
    int b = (int)((sqrtf(8.0f * idx + 1.0f) - 1.0f) * 0.5f);
    while ((b + 1) * (b + 2) / 2 <= idx) b++;
    while (b * (b + 1) / 2 > idx) b--;
    bi = b;
    bj = idx - b * (b + 1) / 2;
}

// ---------------- small kernels ----------------
// fused: batch-mean (xavg) + fp16 transpose xT; reads x once, load-ahead pipelined
__global__ void k_xprep(const float* __restrict__ x) { // grid (NN/32, TT/32), block (32,32)
    __shared__ float tile[32][33];
    int n0 = blockIdx.x * 32, t0 = blockIdx.y * 32;
    int tx = threadIdx.x, ty = threadIdx.y;
    const float* xp = x + (size_t)(t0 + ty) * NN + n0 + tx;
    float cur = xp[0];
    float acc = 0.f;
#pragma unroll
    for (int b = 0; b < BB; b++) {
        acc += cur;
        tile[ty][tx] = cur;
        float nxt = (b + 1 < BB) ? xp[(size_t)(b + 1) * TT * NN] : 0.f;
        __syncthreads();
        g_xT[((size_t)b * NN + n0 + ty) * TT + t0 + tx] = __float2half_rn(tile[tx][ty]);
        __syncthreads();
        cur = nxt;
    }
    g_xavg[(t0 + ty) * NN + n0 + tx] = acc * (1.0f / BB);
}

// fused: parallel column-norm (tree reduce) + fp16 split writes; zeroes g_deg64.
__global__ void k_norm() {      // grid NN/32 = 64, block (32,32)
    __shared__ float red[32][33];
    __shared__ float invn[32];
    __shared__ float tile[32][33];
    int n0 = blockIdx.x * 32;
    int tx = threadIdx.x, ty = threadIdx.y;
    int n = n0 + tx;
    float s = 0.f;
#pragma unroll
    for (int k = 0; k < TT / 32; k++) {
        int t = ty + k * 32;
        float v = g_xavg[t * NN + n];
        s = fmaf(v, v, s);
    }
    red[ty][tx] = s;
    __syncthreads();
#pragma unroll
    for (int off = 16; off > 0; off >>= 1) {
        if (ty < off) red[ty][tx] += red[ty + off][tx];
        __syncthreads();
    }
    if (ty == 0) {
        float nrm = sqrtf(red[0][tx]);
        invn[tx] = 1.0f / fmaxf(nrm, 1e-12f);
    } else if (ty == 1) {
        g_deg64[n] = 0ull;
    }
    __syncthreads();
#pragma unroll
    for (int tb = 0; tb < TT / 32; tb++) {
        int t0 = tb * 32;
        tile[ty][tx] = g_xavg[(t0 + ty) * NN + n0 + tx] * invn[tx];
        __syncthreads();
        int nn = n0 + ty, t = t0 + tx;
        float v = tile[tx][ty];
        __half h = __float2half_rn(v);
        __half l = __float2half_rn(v - __half2float(h));
        size_t base = (size_t)nn * K3;
        g_xa3[base + t] = h; g_xa3[base + TT + t] = l; g_xa3[base + 2 * TT + t] = h;
        g_xb3[base + t] = h; g_xb3[base + TT + t] = h; g_xb3[base + 2 * TT + t] = l;
        __syncthreads();
    }
}

// weight [t][o] -> wT [o][t] fp16
__global__ void k_wT(const float* __restrict__ w) {  // grid (8,8), block (32,32)
    __shared__ float tile[32][33];
    int o0 = blockIdx.x * 32, t0 = blockIdx.y * 32;
    int tx = threadIdx.x, ty = threadIdx.y;
    tile[ty][tx] = w[(t0 + ty) * TT + o0 + tx];
    __syncthreads();
    g_wT[(o0 + ty) * TT + t0 + tx] = __float2half_rn(tile[tx][ty]);
}

// WT[d][s] = fp16(Wn^T) over triangular 32-tile grid; both orientations per tile
__global__ void k_wnT() {         // grid 2080, block (32,32)
    __shared__ unsigned char adjA[32][33];
    __shared__ unsigned char adjB[32][33];
    __shared__ unsigned short cm[32][33];
    __shared__ float dI[32], dJ[32];
    int bi, bj;
    tri_decode(blockIdx.x, bi, bj);
    int tx = threadIdx.x, ty = threadIdx.y;
    int i0 = bi * 32, j0 = bj * 32;
    adjA[ty][tx] = g_adj8[(size_t)(i0 + ty) * NN + j0 + tx];
    adjB[ty][tx] = g_adj8[(size_t)(j0 + ty) * NN + i0 + tx];
    cm[ty][tx]   = g_common16[(size_t)(i0 + ty) * NN + j0 + tx];
    if (ty == 0) {
        float s = (float)g_deg64[i0 + tx];
        dI[tx] = (s > 0.f) ? rsqrtf(s) : 0.f;
    } else if (ty == 1) {
        float s = (float)g_deg64[j0 + tx];
        dJ[tx] = (s > 0.f) ? rsqrtf(s) : 0.f;
    }
    __syncthreads();
    {
        float c = (float)cm[tx][ty];
        float m = (adjA[tx][ty] && c > 1.0f) ? c * c : 0.f;
        float wn = m * dI[tx] * dJ[ty];
        g_WT[(size_t)(j0 + ty) * NN + i0 + tx] = __float2half_rn(wn);
    }
    if (bi != bj) {
        float c = (float)cm[ty][tx];
        float m = (adjB[tx][ty] && c > 1.0f) ? c * c : 0.f;
        float wn = m * dJ[tx] * dI[ty];
        g_WT[(size_t)(i0 + ty) * NN + j0 + tx] = __float2half_rn(wn);
    }
}

// ---------------- HMMA fp16 GEMM: 128x128 tile, 8 warps of 32x64, 4-stage ----------------
enum { HEPI_OUT = 1, HEPI_Y = 2 };

#define TILE_B 10240                 // 128 rows * 80 B
#define STAGE_B (2 * TILE_B)
#define HSMEM_BYTES (4 * STAGE_B)    // 81920

template <int EPI, bool ACC16>
__global__ void __launch_bounds__(256, 2)
hmma_gemm(const __half* __restrict__ A, const __half* __restrict__ B,
          float* __restrict__ C, int K, int lda, int ldb, int ldc,
          size_t strideB, int rowsPerZ,
          const float* __restrict__ bias)
{
    extern __shared__ char dsm[];
    const int tid = threadIdx.x, lane = tid & 31, wid = tid >> 5;
    const int wm = (wid & 3) * 32;
    const int wn = (wid >> 2) * 64;
    const int m0 = blockIdx.y * 128, n0 = blockIdx.x * 128;
    const int rowbase = rowsPerZ * blockIdx.z;

    B += strideB * blockIdx.z;
    const uint32_t s0 = smem_u32(dsm);

    float acc[2][8][4];
#pragma unroll
    for (int i = 0; i < 2; i++)
#pragma unroll
        for (int j = 0; j < 8; j++)
#pragma unroll
            for (int q = 0; q < 4; q++) acc[i][j][q] = 0.f;

    const int nch = K >> 5;
    const int lr = tid >> 2, lu = tid & 3;
    const __half* gA = A + (size_t)(m0 + lr) * lda + lu * 8;
    const __half* gB = B + (size_t)(n0 + lr) * ldb + lu * 8;
    const uint32_t sm_off = lr * 80 + lu * 16;

#define ISSUE(c) do {                                                      \
        int _buf = (c) & 3;                                                \
        uint32_t _da = s0 + _buf * STAGE_B + sm_off;                       \
        uint32_t _db = _da + TILE_B;                                       \
        const __half* _ga = gA + ((size_t)(c) << 5);                       \
        const __half* _gb = gB + ((size_t)(c) << 5);                       \
        CP16(_da, _ga); CP16(_db, _gb);                                    \
        CP16(_da + 64 * 80, _ga + (size_t)64 * lda);                       \
        CP16(_db + 64 * 80, _gb + (size_t)64 * ldb);                       \
        CP_COMMIT();                                                       \
    } while (0)

    ISSUE(0); ISSUE(1); ISSUE(2);

    for (int c = 0; c < nch; c++) {
        CP_WAIT2();
        __syncthreads();
        if (c + 3 < nch) ISSUE(c + 3);

        const uint32_t ba = s0 + (c & 3) * STAGE_B;
        const uint32_t bb = ba + TILE_B;
#pragma unroll
        for (int k16 = 0; k16 < 2; k16++) {
            uint32_t a[2][4], b[8][2];
            {
                int arow = wm + (lane & 15);
                int au = k16 * 2 + (lane >> 4);
                ldsm_x4(a[0][0], a[0][1], a[0][2], a[0][3], ba + arow * 80 + au * 16);
                ldsm_x4(a[1][0], a[1][1], a[1][2], a[1][3], ba + (arow + 16) * 80 + au * 16);
            }
#pragma unroll
            for (int np = 0; np < 4; np++) {
                int brow = wn + np * 16 + (lane & 7) + ((lane >> 4) << 3);
                int bu = k16 * 2 + ((lane >> 3) & 1);
                uint32_t r0, r1, r2, r3;
                ldsm_x4(r0, r1, r2, r3, bb + brow * 80 + bu * 16);
                b[2 * np][0] = r0; b[2 * np][1] = r1;
                b[2 * np + 1][0] = r2; b[2 * np + 1][1] = r3;
            }
#pragma unroll
            for (int mt = 0; mt < 2; mt++)
#pragma unroll
                for (int nt = 0; nt < 8; nt++) {
                    if (ACC16) {
                        uint32_t d[2];
                        mma16816f16(d, a[mt], b[nt]);
                        float2 f0 = __half22float2(*(__half2*)&d[0]);
                        float2 f1 = __half22float2(*(__half2*)&d[1]);
                        acc[mt][nt][0] += f0.x;
                        acc[mt][nt][1] += f0.y;
                        acc[mt][nt][2] += f1.x;
                        acc[mt][nt][3] += f1.y;
                    } else {
                        mma16816(acc[mt][nt], a[mt], b[nt]);
                    }
                }
        }
    }
#undef ISSUE

    const int g = lane >> 2, tig = lane & 3;
#pragma unroll
    for (int mt = 0; mt < 2; mt++) {
#pragma unroll
        for (int half = 0; half < 2; half++) {
            int row = m0 + wm + mt * 16 + g + half * 8;
            int grow = rowbase + row;
#pragma unroll
            for (int nt = 0; nt < 8; nt++) {
                int col = n0 + wn + nt * 8 + 2 * tig;
                float v0 = acc[mt][nt][half * 2 + 0];
                float v1 = acc[mt][nt][half * 2 + 1];
                if (EPI == HEPI_OUT) {
                    float bv = bias[row & (TT - 1)];
                    float2 o;
                    o.x = v0 + bv;
                    o.y = v1 + bv;
                    *(float2*)&C[(size_t)row * ldc + col] = o;
                } else {  // HEPI_Y: single fp16 segment
                    __half2 seg; seg.x = __float2half_rn(v0); seg.y = __float2half_rn(v1);
                    *(__half2*)&g_Y[(size_t)grow * NN + col] = seg;
                }
            }
        }
    }
}

// ---------------- symmetric sim GEMM: lower-tri grid, fused adj + nmask ----------------
__global__ void __launch_bounds__(256, 2)
hmma_sim(const __half* __restrict__ A, const __half* __restrict__ B,
         const float* __restrict__ gumbel)
{
    extern __shared__ char dsm[];
    const int tid = threadIdx.x, lane = tid & 31, wid = tid >> 5;
    const int wm = (wid & 3) * 32;
    const int wn = (wid >> 2) * 64;
    int bi, bj;
    tri_decode(blockIdx.x, bi, bj);
    const int m0 = bi * 128, n0 = bj * 128;
    const int K = K3, lda = K3, ldb = K3;

    const uint32_t s0 = smem_u32(dsm);

    float acc[2][8][4];
#pragma unroll
    for (int i = 0; i < 2; i++)
#pragma unroll
        for (int j = 0; j < 8; j++)
#pragma unroll
            for (int q = 0; q < 4; q++) acc[i][j][q] = 0.f;

    const int nch = K >> 5;
    const int lr = tid >> 2, lu = tid & 3;
    const __half* gA = A + (size_t)(m0 + lr) * lda + lu * 8;
    const __half* gB = B + (size_t)(n0 + lr) * ldb + lu * 8;
    const uint32_t sm_off = lr * 80 + lu * 16;

#define ISSUE(c) do {                                                      \
        int _buf = (c) & 3;                                                \
        uint32_t _da = s0 + _buf * STAGE_B + sm_off;                       \
        uint32_t _db = _da + TILE_B;                                       \
        const __half* _ga = gA + ((size_t)(c) << 5);                       \
        const __half* _gb = gB + ((size_t)(c) << 5);                       \
        CP16(_da, _ga); CP16(_db, _gb);                                    \
        CP16(_da + 64 * 80, _ga + (size_t)64 * lda);                       \
        CP16(_db + 64 * 80, _gb + (size_t)64 * ldb);                       \
        CP_COMMIT();                                                       \
    } while (0)

    ISSUE(0); ISSUE(1); ISSUE(2);

    for (int c = 0; c < nch; c++) {
        CP_WAIT2();
        __syncthreads();
        if (c + 3 < nch) ISSUE(c + 3);

        const uint32_t ba = s0 + (c & 3) * STAGE_B;
        const uint32_t bb = ba + TILE_B;
#pragma unroll
        for (int k16 = 0; k16 < 2; k16++) {
            uint32_t a[2][4], b[8][2];
            {
                int arow = wm + (lane & 15);
                int au = k16 * 2 + (lane >> 4);
                ldsm_x4(a[0][0], a[0][1], a[0][2], a[0][3], ba + arow * 80 + au * 16);
                ldsm_x4(a[1][0], a[1][1], a[1][2], a[1][3], ba + (arow + 16) * 80 + au * 16);
            }
#pragma unroll
            for (int np = 0; np < 4; np++) {
                int brow = wn + np * 16 + (lane & 7) + ((lane >> 4) << 3);
                int bu = k16 * 2 + ((lane >> 3) & 1);
                uint32_t r0, r1, r2, r3;
                ldsm_x4(r0, r1, r2, r3, bb + brow * 80 + bu * 16);
                b[2 * np][0] = r0; b[2 * np][1] = r1;
                b[2 * np + 1][0] = r2; b[2 * np + 1][1] = r3;
            }
#pragma unroll
            for (int mt = 0; mt < 2; mt++)
#pragma unroll
                for (int nt = 0; nt < 8; nt++)
                    mma16816(acc[mt][nt], a[mt], b[nt]);
        }
    }
#undef ISSUE

    // ---- epilogue: stage fp32 sim tile, then coalesced decision passes ----
    __syncthreads();
    float* simS = (float*)dsm;                                    // pitch 129: 66048 B
    uint32_t* bitS = (uint32_t*)(dsm + 66048);                    // 512 u32
    uint32_t* bitT = (uint32_t*)(dsm + 66048 + 2048);             // 512 u32
    const int g = lane >> 2, tig = lane & 3;
#pragma unroll
    for (int mt = 0; mt < 2; mt++)
#pragma unroll
        for (int half = 0; half < 2; half++) {
            int r_loc = wm + mt * 16 + g + half * 8;
#pragma unroll
            for (int nt = 0; nt < 8; nt++) {
                int c_loc = wn + nt * 8 + 2 * tig;
                simS[r_loc * 129 + c_loc]     = acc[mt][nt][half * 2 + 0];
                simS[r_loc * 129 + c_loc + 1] = acc[mt][nt][half * 2 + 1];
            }
        }
    __syncthreads();

    const float2* g2 = (const float2*)gumbel;
    for (int idx = tid; idx < 16384; idx += 256) {
        int r = idx >> 7, c = idx & 127;
        float v = simS[r * 129 + c];
        float s = (v + 1.0f) * 0.5f;
        float2 gg = g2[(size_t)(m0 + r) * NN + (n0 + c)];
        bool arc = (s + gg.x > (1.0f - s) + gg.y);
        unsigned bits = __ballot_sync(0xffffffffu, arc);
        if (lane == 0) bitS[idx >> 5] = bits;
        g_adj8[(size_t)(m0 + r) * NN + n0 + c] = arc ? 1 : 0;
    }
    for (int idx = tid; idx < 16384; idx += 256) {
        int cc = idx >> 7, rr = idx & 127;
        float v = simS[rr * 129 + cc];
        float s = (v + 1.0f) * 0.5f;
        float2 gg = g2[(size_t)(n0 + cc) * NN + (m0 + rr)];
        bool acr = (s + gg.x > (1.0f - s) + gg.y);
        unsigned bits = __ballot_sync(0xffffffffu, acr);
        if (lane == 0) bitT[idx >> 5] = bits;
        g_adj8[(size_t)(n0 + cc) * NN + m0 + rr] = acr ? 1 : 0;
    }
    __syncthreads();
    const bool diag = (m0 == n0);
    for (int idx = tid; idx < 16384; idx += 256) {
        int r = idx >> 7, c = idx & 127;
        unsigned arc = (bitS[idx >> 5] >> (c & 31)) & 1u;
        unsigned acr = (bitT[c * 4 + (r >> 5)] >> (r & 31)) & 1u;
        signed char nm = (diag && r == c) ? 1 : (signed char)(arc | acr);
        g_nm8[(size_t)(m0 + r) * NN + n0 + c] = nm;
    }
    if (!diag) {
        for (int idx = tid; idx < 16384; idx += 256) {
            int cc = idx >> 7, rr = idx & 127;
            unsigned acr = (bitT[idx >> 5] >> (rr & 31)) & 1u;
            unsigned arc = (bitS[rr * 4 + (cc >> 5)] >> (cc & 31)) & 1u;
            g_nm8[(size_t)(n0 + cc) * NN + m0 + rr] = (signed char)(arc | acr);
        }
    }
}

// ---------------- int8 MMA GEMM, symmetric: common = nm @ nm^T (exact, u16) + deg ----------------
#define I8_TILE_B 10240
#define I8_STAGE_B (2 * I8_TILE_B)
#define I8SMEM_BYTES (4 * I8_STAGE_B)    // 81920

__global__ void __launch_bounds__(256, 2)
i8gemm_common(const signed char* __restrict__ A, const signed char* __restrict__ B,
              unsigned short* __restrict__ C, int K, int lda, int ldb, int ldc)
{
    extern __shared__ char dsm[];
    const int tid = threadIdx.x, lane = tid & 31, wid = tid >> 5;
    const int wm = (wid & 3) * 32;
    const int wn = (wid >> 2) * 64;
    int bi, bj;
    tri_decode(blockIdx.x, bi, bj);
    const int m0 = bi * 128, n0 = bj * 128;

    const uint32_t s0 = smem_u32(dsm);

    int acc[2][8][4];
#pragma unroll
    for (int i = 0; i < 2; i++)
#pragma unroll
        for (int j = 0; j < 8; j++)
#pragma unroll
            for (int q = 0; q < 4; q++) acc[i][j][q] = 0;

    const int nch = K >> 6;
    const int lr = tid >> 2, lu = tid & 3;
    const signed char* gA = A + (size_t)(m0 + lr) * lda + lu * 16;
    const signed char* gB = B + (size_t)(n0 + lr) * ldb + lu * 16;
    const uint32_t sm_off = lr * 80 + lu * 16;

#define ISSUE8(c) do {                                                     \
        int _buf = (c) & 3;                                                \
        uint32_t _da = s0 + _buf * I8_STAGE_B + sm_off;                    \
        uint32_t _db = _da + I8_TILE_B;                                    \
        const signed char* _ga = gA + ((size_t)(c) << 6);                  \
        const signed char* _gb = gB + ((size_t)(c) << 6);                  \
        CP16(_da, _ga); CP16(_db, _gb);                                    \
        CP16(_da + 64 * 80, _ga + (size_t)64 * lda);                       \
        CP16(_db + 64 * 80, _gb + (size_t)64 * ldb);                       \
        CP_COMMIT();                                                       \
    } while (0)

    ISSUE8(0); ISSUE8(1); ISSUE8(2);

    for (int c = 0; c < nch; c++) {
        CP_WAIT2();
        __syncthreads();
        if (c + 3 < nch) ISSUE8(c + 3);

        const uint32_t ba = s0 + (c & 3) * I8_STAGE_B;
        const uint32_t bb = ba + I8_TILE_B;
#pragma unroll
        for (int k32 = 0; k32 < 2; k32++) {
            uint32_t a[2][4], b[8][2];
            {
                int arow = wm + (lane & 15);
                int au = k32 * 2 + (lane >> 4);
                ldsm_x4(a[0][0], a[0][1], a[0][2], a[0][3], ba + arow * 80 + au * 16);
                ldsm_x4(a[1][0], a[1][1], a[1][2], a[1][3], ba + (arow + 16) * 80 + au * 16);
            }
#pragma unroll
            for (int np = 0; np < 4; np++) {
                int brow = wn + np * 16 + (lane & 7) + ((lane >> 4) << 3);
                int bu = k32 * 2 + ((lane >> 3) & 1);
                uint32_t r0, r1, r2, r3;
                ldsm_x4(r0, r1, r2, r3, bb + brow * 80 + bu * 16);
                b[2 * np][0] = r0; b[2 * np][1] = r1;
                b[2 * np + 1][0] = r2; b[2 * np + 1][1] = r3;
            }
#pragma unroll
            for (int mt = 0; mt < 2; mt++)
#pragma unroll
                for (int nt = 0; nt < 8; nt++)
                    mma16832s8(acc[mt][nt], a[mt], b[nt]);
        }
    }
#undef ISSUE8

    const int g = lane >> 2, tig = lane & 3;
    const bool offd = (m0 != n0);

    __syncthreads();
    unsigned char* adjS = (unsigned char*)dsm;            // 16384
    unsigned char* adjT = (unsigned char*)dsm + 16384;    // 16384
    unsigned* degC = (unsigned*)(dsm + 32768);            // 512 B
    unsigned* degR = (unsigned*)(dsm + 33280);            // 512 B
    for (int i = tid; i < 1024; i += 256) {
        int r = i >> 3, u = i & 7;
        *(uint4*)(adjS + r * 128 + u * 16) = *(const uint4*)&g_adj8[(size_t)(m0 + r) * NN + n0 + u * 16];
        *(uint4*)(adjT + r * 128 + u * 16) = *(const uint4*)&g_adj8[(size_t)(n0 + r) * NN + m0 + u * 16];
    }
    if (tid < 128) { degC[tid] = 0; degR[tid] = 0; }
    __syncthreads();

#pragma unroll
    for (int mt = 0; mt < 2; mt++) {
#pragma unroll
        for (int half = 0; half < 2; half++) {
            int r_loc = wm + mt * 16 + g + half * 8;
            unsigned rowsum = 0;
#pragma unroll
            for (int nt = 0; nt < 8; nt++) {
                int c_loc = wn + nt * 8 + 2 * tig;
                int v0 = acc[mt][nt][half * 2 + 0];
                int v1 = acc[mt][nt][half * 2 + 1];
                ushort2 o; o.x = (unsigned short)v0; o.y = (unsigned short)v1;
                *(ushort2*)&C[(size_t)(m0 + r_loc) * ldc + n0 + c_loc] = o;
                unsigned s0v = (v0 > 1 && adjS[r_loc * 128 + c_loc])     ? (unsigned)(v0 * v0) : 0u;
                unsigned s1v = (v1 > 1 && adjS[r_loc * 128 + c_loc + 1]) ? (unsigned)(v1 * v1) : 0u;
                s0v += __shfl_down_sync(0xffffffffu, s0v, 16);
                s0v += __shfl_down_sync(0xffffffffu, s0v, 8);
                s0v += __shfl_down_sync(0xffffffffu, s0v, 4);
                s1v += __shfl_down_sync(0xffffffffu, s1v, 16);
                s1v += __shfl_down_sync(0xffffffffu, s1v, 8);
                s1v += __shfl_down_sync(0xffffffffu, s1v, 4);
                if (g == 0) {
                    atomicAdd(&degC[c_loc], s0v);
                    atomicAdd(&degC[c_loc + 1], s1v);
                }
                if (offd) {
                    unsigned t0 = (v0 > 1 && adjT[(c_loc) * 128 + r_loc])     ? (unsigned)(v0 * v0) : 0u;
                    unsigned t1 = (v1 > 1 && adjT[(c_loc + 1) * 128 + r_loc]) ? (unsigned)(v1 * v1) : 0u;
                    rowsum += t0 + t1;
                }
            }
            if (offd) {
                rowsum += __shfl_down_sync(0xffffffffu, rowsum, 2);
                rowsum += __shfl_down_sync(0xffffffffu, rowsum, 1);
                if (tig == 0) atomicAdd(&degR[r_loc], rowsum);
            }
        }
    }
    __syncthreads();

    if (tid < 128) {
        atomicAdd(&g_deg64[n0 + tid], (unsigned long long)degC[tid]);
        if (offd) atomicAdd(&g_deg64[m0 + tid], (unsigned long long)degR[tid]);
    }
}

// ---------------- launcher ----------------
extern "C" void kernel_launch(void* const* d_in, const int* in_sizes, int n_in,
                              void* d_out, int out_size)
{
    const float* x      = (const float*)d_in[0];   // [B,T,N]
    const float* weight = (const float*)d_in[1];   // [T,T]
    const float* bias   = (const float*)d_in[2];   // [T]
    const float* gumbel = (const float*)d_in[3];   // [N*N, 2]
    float* out = (float*)d_out;                    // [B,T,N] = [4096][2048]

    __half *p_xa3, *p_xb3, *p_wt, *p_y, *p_wT, *p_xT;
    signed char* p_nm8;
    unsigned short* p_common16;
    cudaGetSymbolAddress((void**)&p_xa3,      g_xa3);
    cudaGetSymbolAddress((void**)&p_xb3,      g_xb3);
    cudaGetSymbolAddress((void**)&p_nm8,      g_nm8);
    cudaGetSymbolAddress((void**)&p_wt,       g_WT);
    cudaGetSymbolAddress((void**)&p_y,        g_Y);
    cudaGetSymbolAddress((void**)&p_wT,       g_wT);
    cudaGetSymbolAddress((void**)&p_xT,       g_xT);
    cudaGetSymbolAddress((void**)&p_common16, g_common16);

    cudaFuncSetAttribute((const void*)hmma_gemm<HEPI_OUT, true>,  cudaFuncAttributeMaxDynamicSharedMemorySize, HSMEM_BYTES);
    cudaFuncSetAttribute((const void*)hmma_gemm<HEPI_Y, false>,   cudaFuncAttributeMaxDynamicSharedMemorySize, HSMEM_BYTES);
    cudaFuncSetAttribute((const void*)hmma_sim,                   cudaFuncAttributeMaxDynamicSharedMemorySize, HSMEM_BYTES);
    cudaFuncSetAttribute((const void*)i8gemm_common,              cudaFuncAttributeMaxDynamicSharedMemorySize, I8SMEM_BYTES);

    // persistent side stream + events for fork-join capture (host handles only)
    static cudaStream_t sB = nullptr;
    static cudaEvent_t evFork = nullptr, evX = nullptr, evJoin = nullptr;
    if (sB == nullptr) {
        cudaStreamCreateWithFlags(&sB, cudaStreamNonBlocking);
        cudaEventCreateWithFlags(&evFork, cudaEventDisableTiming);
        cudaEventCreateWithFlags(&evX,    cudaEventDisableTiming);
        cudaEventCreateWithFlags(&evJoin, cudaEventDisableTiming);
    }

    // ---- fork: weight transpose on sB ----
    cudaEventRecord(evFork, 0);
    cudaStreamWaitEvent(sB, evFork, 0);
    {
        dim3 grid(TT / 32, TT / 32); dim3 blk(32, 32);
        k_wT<<<grid, blk, 0, sB>>>(weight);
    }

    // ---- default: fused x prep ----
    {
        dim3 grid(NN / 32, TT / 32); dim3 blk(32, 32);
        k_xprep<<<grid, blk>>>(x);
    }
    cudaEventRecord(evX, 0);

    // ---- sB: Y GEMM (needs xT + wT), f32 accumulate ----
    cudaStreamWaitEvent(sB, evX, 0);
    {
        dim3 grid(NN / 128, TT / 128, BB);
        hmma_gemm<HEPI_Y, false><<<grid, 256, HSMEM_BYTES, sB>>>(
            p_wT, p_xT, nullptr, TT, TT, TT, NN,
            (size_t)NN * TT, TT, nullptr);
    }
    cudaEventRecord(evJoin, sB);

    // ---- adjacency chain on default stream ----
    {
        dim3 blk(32, 32);
        k_norm<<<NN / 32, blk>>>();
    }
    {
        const int NTILES = (NN / 128) * (NN / 128 + 1) / 2;   // 136
        hmma_sim<<<NTILES, 256, HSMEM_BYTES>>>(p_xa3, p_xb3, gumbel);
    }
    {
        const int NTILES = (NN / 128) * (NN / 128 + 1) / 2;   // 136
        i8gemm_common<<<NTILES, 256, I8SMEM_BYTES>>>(p_nm8, p_nm8, p_common16, NN, NN, NN, NN);
    }
    {
        const int NTILES32 = (NN / 32) * (NN / 32 + 1) / 2;   // 2080
        dim3 blk(32, 32);
        k_wnT<<<NTILES32, blk>>>();
    }

    // ---- join: out GEMM needs g_Y (sB) + g_WT (default) ----
    cudaStreamWaitEvent(0, evJoin, 0);

    // out = Y @ Wn + bias  (fp16 operands, f16-mma + per-mma f32 promote, K=2048)
    {
        dim3 grid(NN / 128, (BB * TT) / 128);
        hmma_gemm<HEPI_OUT, true><<<grid, 256, HSMEM_BYTES>>>(
            p_y, p_wt, out, NN, NN, NN, NN, 0, 0, bias);
    }
}

// round 15
// speedup vs baseline: 1.1028x; 1.1028x over previous
#include <cuda_runtime.h>
#include <cuda_fp16.h>
#include <cstdint>
#include <cstddef>

#define NN 2048      // nodes
#define BB 16        // batch
#define TT 256       // time/feature dim
#define K3 (3*TT)    // 768  (sim split K)

// ---------------- device scratch (no allocations allowed) ----------------
__device__ float g_xavg[TT * NN];                  // [t][n]
__device__ __half g_xa3[(size_t)NN * K3];          // [n][768] = [h, l, h]
__device__ __half g_xb3[(size_t)NN * K3];          // [n][768] = [h, h, l]
__device__ __half g_wT[TT * TT];                   // [o][t] fp16
__device__ __half g_xT[(size_t)BB * NN * TT];      // [b][n][t] fp16
__device__ unsigned char g_adj8[(size_t)NN * NN];  // directed adjacency 0/1
__device__ signed char g_nm8[(size_t)NN * NN];     // nmask 0/1 (s8)
__device__ unsigned short g_common16[(size_t)NN * NN]; // exact counts, lower-tri valid
__device__ __half g_WT[(size_t)NN * NN];           // [d][s] = fp16(Wn^T)
__device__ __half g_Y[(size_t)BB * TT * NN];       // [4096][2048] fp16(Y)
__device__ unsigned long long g_deg64[NN];         // exact integer deg sums

// ---------------- PTX helpers (sm_80-level features only) ----------------
__device__ __forceinline__ uint32_t smem_u32(const void* p) {
    uint32_t a;
    asm("{ .reg .u64 t; cvta.to.shared.u64 t, %1; cvt.u32.u64 %0, t; }"
        : "=r"(a) : "l"(p));
    return a;
}

#define CP16(dst, src) \
    asm volatile("cp.async.cg.shared.global [%0], [%1], 16;" :: "r"(dst), "l"(src))
#define CP_COMMIT() asm volatile("cp.async.commit_group;" ::: "memory")
#define CP_WAIT2()  asm volatile("cp.async.wait_group 2;" ::: "memory")

__device__ __forceinline__ void ldsm_x4(uint32_t& r0, uint32_t& r1, uint32_t& r2,
                                        uint32_t& r3, uint32_t addr) {
    asm volatile("ldmatrix.sync.aligned.m8n8.x4.shared.b16 {%0,%1,%2,%3}, [%4];"
                 : "=r"(r0), "=r"(r1), "=r"(r2), "=r"(r3) : "r"(addr));
}

__device__ __forceinline__ void mma16816(float* c, const uint32_t* a, const uint32_t* b) {
    asm volatile(
        "mma.sync.aligned.m16n8k16.row.col.f32.f16.f16.f32 "
        "{%0,%1,%2,%3}, {%4,%5,%6,%7}, {%8,%9}, {%0,%1,%2,%3};"
        : "+f"(c[0]), "+f"(c[1]), "+f"(c[2]), "+f"(c[3])
        : "r"(a[0]), "r"(a[1]), "r"(a[2]), "r"(a[3]), "r"(b[0]), "r"(b[1]));
}

__device__ __forceinline__ void mma16832s8(int* c, const uint32_t* a, const uint32_t* b) {
    asm volatile(
        "mma.sync.aligned.m16n8k32.row.col.s32.s8.s8.s32 "
        "{%0,%1,%2,%3}, {%4,%5,%6,%7}, {%8,%9}, {%0,%1,%2,%3};"
        : "+r"(c[0]), "+r"(c[1]), "+r"(c[2]), "+r"(c[3])
        : "r"(a[0]), "r"(a[1]), "r"(a[2]), "r"(a[3]), "r"(b[0]), "r"(b[1]));
}

// decode 1D lower-triangle index -> (bi >= bj)
__device__ __forceinline__ void tri_decode(int idx, int& bi, int& bj) {
    int b = (int)((sqrtf(8.0f * idx + 1.0f) - 1.0f) * 0.5f);
    while ((b + 1) * (b + 2) / 2 <= idx) b++;
    while (b * (b + 1) / 2 > idx) b--;
    bi = b;
    bj = idx - b * (b + 1) / 2;
}

// ---------------- small kernels ----------------
// fused: batch-mean (xavg) + fp16 transpose xT; reads x once; double-buffered tiles
__global__ void k_xprep(const float* __restrict__ x) { // grid (NN/32, TT/32), block (32,32)
    __shared__ float tile[2][32][33];
    int n0 = blockIdx.x * 32, t0 = blockIdx.y * 32;
    int tx = threadIdx.x, ty = threadIdx.y;
    const float* xp = x + (size_t)(t0 + ty) * NN + n0 + tx;
    float cur = xp[0];
    float acc = 0.f;
#pragma unroll
    for (int b = 0; b < BB; b++) {
        acc += cur;
        tile[b & 1][ty][tx] = cur;
        float nxt = (b + 1 < BB) ? xp[(size_t)(b + 1) * TT * NN] : 0.f;
        __syncthreads();
        g_xT[((size_t)b * NN + n0 + ty) * TT + t0 + tx] = __float2half_rn(tile[b & 1][tx][ty]);
        cur = nxt;
    }
    g_xavg[(t0 + ty) * NN + n0 + tx] = acc * (1.0f / BB);
}

// fused: parallel column-norm (tree reduce) + fp16 split writes; zeroes g_deg64.
__global__ void k_norm() {      // grid NN/32 = 64, block (32,32)
    __shared__ float red[32][33];
    __shared__ float invn[32];
    __shared__ float tile[32][33];
    int n0 = blockIdx.x * 32;
    int tx = threadIdx.x, ty = threadIdx.y;
    int n = n0 + tx;
    float s = 0.f;
#pragma unroll
    for (int k = 0; k < TT / 32; k++) {
        int t = ty + k * 32;
        float v = g_xavg[t * NN + n];
        s = fmaf(v, v, s);
    }
    red[ty][tx] = s;
    __syncthreads();
#pragma unroll
    for (int off = 16; off > 0; off >>= 1) {
        if (ty < off) red[ty][tx] += red[ty + off][tx];
        __syncthreads();
    }
    if (ty == 0) {
        float nrm = sqrtf(red[0][tx]);
        invn[tx] = 1.0f / fmaxf(nrm, 1e-12f);
    } else if (ty == 1) {
        g_deg64[n] = 0ull;
    }
    __syncthreads();
#pragma unroll
    for (int tb = 0; tb < TT / 32; tb++) {
        int t0 = tb * 32;
        tile[ty][tx] = g_xavg[(t0 + ty) * NN + n0 + tx] * invn[tx];
        __syncthreads();
        int nn = n0 + ty, t = t0 + tx;
        float v = tile[tx][ty];
        __half h = __float2half_rn(v);
        __half l = __float2half_rn(v - __half2float(h));
        size_t base = (size_t)nn * K3;
        g_xa3[base + t] = h; g_xa3[base + TT + t] = l; g_xa3[base + 2 * TT + t] = h;
        g_xb3[base + t] = h; g_xb3[base + TT + t] = h; g_xb3[base + 2 * TT + t] = l;
        __syncthreads();
    }
}

// weight [t][o] -> wT [o][t] fp16
__global__ void k_wT(const float* __restrict__ w) {  // grid (8,8), block (32,32)
    __shared__ float tile[32][33];
    int o0 = blockIdx.x * 32, t0 = blockIdx.y * 32;
    int tx = threadIdx.x, ty = threadIdx.y;
    tile[ty][tx] = w[(t0 + ty) * TT + o0 + tx];
    __syncthreads();
    g_wT[(o0 + ty) * TT + t0 + tx] = __float2half_rn(tile[tx][ty]);
}

// WT[d][s] = fp16(Wn^T) over triangular 32-tile grid; both orientations per tile
__global__ void k_wnT() {         // grid 2080, block (32,32)
    __shared__ unsigned char adjA[32][33];
    __shared__ unsigned char adjB[32][33];
    __shared__ unsigned short cm[32][33];
    __shared__ float dI[32], dJ[32];
    int bi, bj;
    tri_decode(blockIdx.x, bi, bj);
    int tx = threadIdx.x, ty = threadIdx.y;
    int i0 = bi * 32, j0 = bj * 32;
    adjA[ty][tx] = g_adj8[(size_t)(i0 + ty) * NN + j0 + tx];
    adjB[ty][tx] = g_adj8[(size_t)(j0 + ty) * NN + i0 + tx];
    cm[ty][tx]   = g_common16[(size_t)(i0 + ty) * NN + j0 + tx];
    if (ty == 0) {
        float s = (float)g_deg64[i0 + tx];
        dI[tx] = (s > 0.f) ? rsqrtf(s) : 0.f;
    } else if (ty == 1) {
        float s = (float)g_deg64[j0 + tx];
        dJ[tx] = (s > 0.f) ? rsqrtf(s) : 0.f;
    }
    __syncthreads();
    {
        float c = (float)cm[tx][ty];
        float m = (adjA[tx][ty] && c > 1.0f) ? c * c : 0.f;
        float wn = m * dI[tx] * dJ[ty];
        g_WT[(size_t)(j0 + ty) * NN + i0 + tx] = __float2half_rn(wn);
    }
    if (bi != bj) {
        float c = (float)cm[ty][tx];
        float m = (adjB[tx][ty] && c > 1.0f) ? c * c : 0.f;
        float wn = m * dJ[tx] * dI[ty];
        g_WT[(size_t)(i0 + ty) * NN + j0 + tx] = __float2half_rn(wn);
    }
}

// ---------------- HMMA fp16 GEMM: 128x128 tile, 8 warps of 32x64, 4-stage ----------------
enum { HEPI_OUT = 1, HEPI_Y = 2 };

#define TILE_B 10240                 // 128 rows * 80 B
#define STAGE_B (2 * TILE_B)
#define HSMEM_BYTES (4 * STAGE_B)    // 81920

template <int EPI>
__global__ void __launch_bounds__(256, 2)
hmma_gemm(const __half* __restrict__ A, const __half* __restrict__ B,
          float* __restrict__ C, int K, int lda, int ldb, int ldc,
          size_t strideB, int rowsPerZ,
          const float* __restrict__ bias)
{
    extern __shared__ char dsm[];
    const int tid = threadIdx.x, lane = tid & 31, wid = tid >> 5;
    const int wm = (wid & 3) * 32;
    const int wn = (wid >> 2) * 64;
    const int m0 = blockIdx.y * 128, n0 = blockIdx.x * 128;
    const int rowbase = rowsPerZ * blockIdx.z;

    B += strideB * blockIdx.z;
    const uint32_t s0 = smem_u32(dsm);

    float acc[2][8][4];
#pragma unroll
    for (int i = 0; i < 2; i++)
#pragma unroll
        for (int j = 0; j < 8; j++)
#pragma unroll
            for (int q = 0; q < 4; q++) acc[i][j][q] = 0.f;

    const int nch = K >> 5;
    const int lr = tid >> 2, lu = tid & 3;
    const __half* gA = A + (size_t)(m0 + lr) * lda + lu * 8;
    const __half* gB = B + (size_t)(n0 + lr) * ldb + lu * 8;
    const uint32_t sm_off = lr * 80 + lu * 16;

#define ISSUE(c) do {                                                      \
        int _buf = (c) & 3;                                                \
        uint32_t _da = s0 + _buf * STAGE_B + sm_off;                       \
        uint32_t _db = _da + TILE_B;                                       \
        const __half* _ga = gA + ((size_t)(c) << 5);                       \
        const __half* _gb = gB + ((size_t)(c) << 5);                       \
        CP16(_da, _ga); CP16(_db, _gb);                                    \
        CP16(_da + 64 * 80, _ga + (size_t)64 * lda);                       \
        CP16(_db + 64 * 80, _gb + (size_t)64 * ldb);                       \
        CP_COMMIT();                                                       \
    } while (0)

    ISSUE(0); ISSUE(1); ISSUE(2);

    for (int c = 0; c < nch; c++) {
        CP_WAIT2();
        __syncthreads();
        if (c + 3 < nch) ISSUE(c + 3);

        const uint32_t ba = s0 + (c & 3) * STAGE_B;
        const uint32_t bb = ba + TILE_B;
#pragma unroll
        for (int k16 = 0; k16 < 2; k16++) {
            uint32_t a[2][4], b[8][2];
            {
                int arow = wm + (lane & 15);
                int au = k16 * 2 + (lane >> 4);
                ldsm_x4(a[0][0], a[0][1], a[0][2], a[0][3], ba + arow * 80 + au * 16);
                ldsm_x4(a[1][0], a[1][1], a[1][2], a[1][3], ba + (arow + 16) * 80 + au * 16);
            }
#pragma unroll
            for (int np = 0; np < 4; np++) {
                int brow = wn + np * 16 + (lane & 7) + ((lane >> 4) << 3);
                int bu = k16 * 2 + ((lane >> 3) & 1);
                uint32_t r0, r1, r2, r3;
                ldsm_x4(r0, r1, r2, r3, bb + brow * 80 + bu * 16);
                b[2 * np][0] = r0; b[2 * np][1] = r1;
                b[2 * np + 1][0] = r2; b[2 * np + 1][1] = r3;
            }
#pragma unroll
            for (int mt = 0; mt < 2; mt++)
#pragma unroll
                for (int nt = 0; nt < 8; nt++)
                    mma16816(acc[mt][nt], a[mt], b[nt]);
        }
    }
#undef ISSUE

    const int g = lane >> 2, tig = lane & 3;
#pragma unroll
    for (int mt = 0; mt < 2; mt++) {
#pragma unroll
        for (int half = 0; half < 2; half++) {
            int row = m0 + wm + mt * 16 + g + half * 8;
            int grow = rowbase + row;
#pragma unroll
            for (int nt = 0; nt < 8; nt++) {
                int col = n0 + wn + nt * 8 + 2 * tig;
                float v0 = acc[mt][nt][half * 2 + 0];
                float v1 = acc[mt][nt][half * 2 + 1];
                if (EPI == HEPI_OUT) {
                    float bv = bias[row & (TT - 1)];
                    float2 o;
                    o.x = v0 + bv;
                    o.y = v1 + bv;
                    *(float2*)&C[(size_t)row * ldc + col] = o;
                } else {  // HEPI_Y: single fp16 segment
                    __half2 seg; seg.x = __float2half_rn(v0); seg.y = __float2half_rn(v1);
                    *(__half2*)&g_Y[(size_t)grow * NN + col] = seg;
                }
            }
        }
    }
}

// ---------------- symmetric sim GEMM: lower-tri grid, fused adj + nmask ----------------
__global__ void __launch_bounds__(256, 2)
hmma_sim(const __half* __restrict__ A, const __half* __restrict__ B,
         const float* __restrict__ gumbel)
{
    extern __shared__ char dsm[];
    const int tid = threadIdx.x, lane = tid & 31, wid = tid >> 5;
    const int wm = (wid & 3) * 32;
    const int wn = (wid >> 2) * 64;
    int bi, bj;
    tri_decode(blockIdx.x, bi, bj);
    const int m0 = bi * 128, n0 = bj * 128;
    const int K = K3, lda = K3, ldb = K3;

    const uint32_t s0 = smem_u32(dsm);

    float acc[2][8][4];
#pragma unroll
    for (int i = 0; i < 2; i++)
#pragma unroll
        for (int j = 0; j < 8; j++)
#pragma unroll
            for (int q = 0; q < 4; q++) acc[i][j][q] = 0.f;

    const int nch = K >> 5;
    const int lr = tid >> 2, lu = tid & 3;
    const __half* gA = A + (size_t)(m0 + lr) * lda + lu * 8;
    const __half* gB = B + (size_t)(n0 + lr) * ldb + lu * 8;
    const uint32_t sm_off = lr * 80 + lu * 16;

#define ISSUE(c) do {                                                      \
        int _buf = (c) & 3;                                                \
        uint32_t _da = s0 + _buf * STAGE_B + sm_off;                       \
        uint32_t _db = _da + TILE_B;                                       \
        const __half* _ga = gA + ((size_t)(c) << 5);                       \
        const __half* _gb = gB + ((size_t)(c) << 5);                       \
        CP16(_da, _ga); CP16(_db, _gb);                                    \
        CP16(_da + 64 * 80, _ga + (size_t)64 * lda);                       \
        CP16(_db + 64 * 80, _gb + (size_t)64 * ldb);                       \
        CP_COMMIT();                                                       \
    } while (0)

    ISSUE(0); ISSUE(1); ISSUE(2);

    for (int c = 0; c < nch; c++) {
        CP_WAIT2();
        __syncthreads();
        if (c + 3 < nch) ISSUE(c + 3);

        const uint32_t ba = s0 + (c & 3) * STAGE_B;
        const uint32_t bb = ba + TILE_B;
#pragma unroll
        for (int k16 = 0; k16 < 2; k16++) {
            uint32_t a[2][4], b[8][2];
            {
                int arow = wm + (lane & 15);
                int au = k16 * 2 + (lane >> 4);
                ldsm_x4(a[0][0], a[0][1], a[0][2], a[0][3], ba + arow * 80 + au * 16);
                ldsm_x4(a[1][0], a[1][1], a[1][2], a[1][3], ba + (arow + 16) * 80 + au * 16);
            }
#pragma unroll
            for (int np = 0; np < 4; np++) {
                int brow = wn + np * 16 + (lane & 7) + ((lane >> 4) << 3);
                int bu = k16 * 2 + ((lane >> 3) & 1);
                uint32_t r0, r1, r2, r3;
                ldsm_x4(r0, r1, r2, r3, bb + brow * 80 + bu * 16);
                b[2 * np][0] = r0; b[2 * np][1] = r1;
                b[2 * np + 1][0] = r2; b[2 * np + 1][1] = r3;
            }
#pragma unroll
            for (int mt = 0; mt < 2; mt++)
#pragma unroll
                for (int nt = 0; nt < 8; nt++)
                    mma16816(acc[mt][nt], a[mt], b[nt]);
        }
    }
#undef ISSUE

    // ---- epilogue: stage fp32 sim tile, then coalesced decision passes ----
    __syncthreads();
    float* simS = (float*)dsm;                                    // pitch 129: 66048 B
    uint32_t* bitS = (uint32_t*)(dsm + 66048);                    // 512 u32
    uint32_t* bitT = (uint32_t*)(dsm + 66048 + 2048);             // 512 u32
    const int g = lane >> 2, tig = lane & 3;
#pragma unroll
    for (int mt = 0; mt < 2; mt++)
#pragma unroll
        for (int half = 0; half < 2; half++) {
            int r_loc = wm + mt * 16 + g + half * 8;
#pragma unroll
            for (int nt = 0; nt < 8; nt++) {
                int c_loc = wn + nt * 8 + 2 * tig;
                simS[r_loc * 129 + c_loc]     = acc[mt][nt][half * 2 + 0];
                simS[r_loc * 129 + c_loc + 1] = acc[mt][nt][half * 2 + 1];
            }
        }
    __syncthreads();

    const float2* g2 = (const float2*)gumbel;
    for (int idx = tid; idx < 16384; idx += 256) {
        int r = idx >> 7, c = idx & 127;
        float v = simS[r * 129 + c];
        float s = (v + 1.0f) * 0.5f;
        float2 gg = g2[(size_t)(m0 + r) * NN + (n0 + c)];
        bool arc = (s + gg.x > (1.0f - s) + gg.y);
        unsigned bits = __ballot_sync(0xffffffffu, arc);
        if (lane == 0) bitS[idx >> 5] = bits;
        g_adj8[(size_t)(m0 + r) * NN + n0 + c] = arc ? 1 : 0;
    }
    for (int idx = tid; idx < 16384; idx += 256) {
        int cc = idx >> 7, rr = idx & 127;
        float v = simS[rr * 129 + cc];
        float s = (v + 1.0f) * 0.5f;
        float2 gg = g2[(size_t)(n0 + cc) * NN + (m0 + rr)];
        bool acr = (s + gg.x > (1.0f - s) + gg.y);
        unsigned bits = __ballot_sync(0xffffffffu, acr);
        if (lane == 0) bitT[idx >> 5] = bits;
        g_adj8[(size_t)(n0 + cc) * NN + m0 + rr] = acr ? 1 : 0;
    }
    __syncthreads();
    const bool diag = (m0 == n0);
    for (int idx = tid; idx < 16384; idx += 256) {
        int r = idx >> 7, c = idx & 127;
        unsigned arc = (bitS[idx >> 5] >> (c & 31)) & 1u;
        unsigned acr = (bitT[c * 4 + (r >> 5)] >> (r & 31)) & 1u;
        signed char nm = (diag && r == c) ? 1 : (signed char)(arc | acr);
        g_nm8[(size_t)(m0 + r) * NN + n0 + c] = nm;
    }
    if (!diag) {
        for (int idx = tid; idx < 16384; idx += 256) {
            int cc = idx >> 7, rr = idx & 127;
            unsigned acr = (bitT[idx >> 5] >> (rr & 31)) & 1u;
            unsigned arc = (bitS[rr * 4 + (cc >> 5)] >> (cc & 31)) & 1u;
            g_nm8[(size_t)(n0 + cc) * NN + m0 + rr] = (signed char)(arc | acr);
        }
    }
}

// ---------------- int8 MMA GEMM, symmetric: common = nm @ nm^T (exact, u16) + deg ----------------
#define I8_TILE_B 10240
#define I8_STAGE_B (2 * I8_TILE_B)
#define I8SMEM_BYTES (4 * I8_STAGE_B)    // 81920

__global__ void __launch_bounds__(256, 2)
i8gemm_common(const signed char* __restrict__ A, const signed char* __restrict__ B,
              unsigned short* __restrict__ C, int K, int lda, int ldb, int ldc)
{
    extern __shared__ char dsm[];
    const int tid = threadIdx.x, lane = tid & 31, wid = tid >> 5;
    const int wm = (wid & 3) * 32;
    const int wn = (wid >> 2) * 64;
    int bi, bj;
    tri_decode(blockIdx.x, bi, bj);
    const int m0 = bi * 128, n0 = bj * 128;

    const uint32_t s0 = smem_u32(dsm);

    int acc[2][8][4];
#pragma unroll
    for (int i = 0; i < 2; i++)
#pragma unroll
        for (int j = 0; j < 8; j++)
#pragma unroll
            for (int q = 0; q < 4; q++) acc[i][j][q] = 0;

    const int nch = K >> 6;
    const int lr = tid >> 2, lu = tid & 3;
    const signed char* gA = A + (size_t)(m0 + lr) * lda + lu * 16;
    const signed char* gB = B + (size_t)(n0 + lr) * ldb + lu * 16;
    const uint32_t sm_off = lr * 80 + lu * 16;

#define ISSUE8(c) do {                                                     \
        int _buf = (c) & 3;                                                \
        uint32_t _da = s0 + _buf * I8_STAGE_B + sm_off;                    \
        uint32_t _db = _da + I8_TILE_B;                                    \
        const signed char* _ga = gA + ((size_t)(c) << 6);                  \
        const signed char* _gb = gB + ((size_t)(c) << 6);                  \
        CP16(_da, _ga); CP16(_db, _gb);                                    \
        CP16(_da + 64 * 80, _ga + (size_t)64 * lda);                       \
        CP16(_db + 64 * 80, _gb + (size_t)64 * ldb);                       \
        CP_COMMIT();                                                       \
    } while (0)

    ISSUE8(0); ISSUE8(1); ISSUE8(2);

    for (int c = 0; c < nch; c++) {
        CP_WAIT2();
        __syncthreads();
        if (c + 3 < nch) ISSUE8(c + 3);

        const uint32_t ba = s0 + (c & 3) * I8_STAGE_B;
        const uint32_t bb = ba + I8_TILE_B;
#pragma unroll
        for (int k32 = 0; k32 < 2; k32++) {
            uint32_t a[2][4], b[8][2];
            {
                int arow = wm + (lane & 15);
                int au = k32 * 2 + (lane >> 4);
                ldsm_x4(a[0][0], a[0][1], a[0][2], a[0][3], ba + arow * 80 + au * 16);
                ldsm_x4(a[1][0], a[1][1], a[1][2], a[1][3], ba + (arow + 16) * 80 + au * 16);
            }
#pragma unroll
            for (int np = 0; np < 4; np++) {
                int brow = wn + np * 16 + (lane & 7) + ((lane >> 4) << 3);
                int bu = k32 * 2 + ((lane >> 3) & 1);
                uint32_t r0, r1, r2, r3;
                ldsm_x4(r0, r1, r2, r3, bb + brow * 80 + bu * 16);
                b[2 * np][0] = r0; b[2 * np][1] = r1;
                b[2 * np + 1][0] = r2; b[2 * np + 1][1] = r3;
            }
#pragma unroll
            for (int mt = 0; mt < 2; mt++)
#pragma unroll
                for (int nt = 0; nt < 8; nt++)
                    mma16832s8(acc[mt][nt], a[mt], b[nt]);
        }
    }
#undef ISSUE8

    const int g = lane >> 2, tig = lane & 3;
    const bool offd = (m0 != n0);

    __syncthreads();
    unsigned char* adjS = (unsigned char*)dsm;            // 16384
    unsigned char* adjT = (unsigned char*)dsm + 16384;    // 16384
    unsigned* degC = (unsigned*)(dsm + 32768);            // 512 B
    unsigned* degR = (unsigned*)(dsm + 33280);            // 512 B
    for (int i = tid; i < 1024; i += 256) {
        int r = i >> 3, u = i & 7;
        *(uint4*)(adjS + r * 128 + u * 16) = *(const uint4*)&g_adj8[(size_t)(m0 + r) * NN + n0 + u * 16];
        *(uint4*)(adjT + r * 128 + u * 16) = *(const uint4*)&g_adj8[(size_t)(n0 + r) * NN + m0 + u * 16];
    }
    if (tid < 128) { degC[tid] = 0; degR[tid] = 0; }
    __syncthreads();

#pragma unroll
    for (int mt = 0; mt < 2; mt++) {
#pragma unroll
        for (int half = 0; half < 2; half++) {
            int r_loc = wm + mt * 16 + g + half * 8;
            unsigned rowsum = 0;
#pragma unroll
            for (int nt = 0; nt < 8; nt++) {
                int c_loc = wn + nt * 8 + 2 * tig;
                int v0 = acc[mt][nt][half * 2 + 0];
                int v1 = acc[mt][nt][half * 2 + 1];
                ushort2 o; o.x = (unsigned short)v0; o.y = (unsigned short)v1;
                *(ushort2*)&C[(size_t)(m0 + r_loc) * ldc + n0 + c_loc] = o;
                unsigned s0v = (v0 > 1 && adjS[r_loc * 128 + c_loc])     ? (unsigned)(v0 * v0) : 0u;
                unsigned s1v = (v1 > 1 && adjS[r_loc * 128 + c_loc + 1]) ? (unsigned)(v1 * v1) : 0u;
                s0v += __shfl_down_sync(0xffffffffu, s0v, 16);
                s0v += __shfl_down_sync(0xffffffffu, s0v, 8);
                s0v += __shfl_down_sync(0xffffffffu, s0v, 4);
                s1v += __shfl_down_sync(0xffffffffu, s1v, 16);
                s1v += __shfl_down_sync(0xffffffffu, s1v, 8);
                s1v += __shfl_down_sync(0xffffffffu, s1v, 4);
                if (g == 0) {
                    atomicAdd(&degC[c_loc], s0v);
                    atomicAdd(&degC[c_loc + 1], s1v);
                }
                if (offd) {
                    unsigned t0 = (v0 > 1 && adjT[(c_loc) * 128 + r_loc])     ? (unsigned)(v0 * v0) : 0u;
                    unsigned t1 = (v1 > 1 && adjT[(c_loc + 1) * 128 + r_loc]) ? (unsigned)(v1 * v1) : 0u;
                    rowsum += t0 + t1;
                }
            }
            if (offd) {
                rowsum += __shfl_down_sync(0xffffffffu, rowsum, 2);
                rowsum += __shfl_down_sync(0xffffffffu, rowsum, 1);
                if (tig == 0) atomicAdd(&degR[r_loc], rowsum);
            }
        }
    }
    __syncthreads();

    if (tid < 128) {
        atomicAdd(&g_deg64[n0 + tid], (unsigned long long)degC[tid]);
        if (offd) atomicAdd(&g_deg64[m0 + tid], (unsigned long long)degR[tid]);
    }
}

// ---------------- launcher ----------------
extern "C" void kernel_launch(void* const* d_in, const int* in_sizes, int n_in,
                              void* d_out, int out_size)
{
    const float* x      = (const float*)d_in[0];   // [B,T,N]
    const float* weight = (const float*)d_in[1];   // [T,T]
    const float* bias   = (const float*)d_in[2];   // [T]
    const float* gumbel = (const float*)d_in[3];   // [N*N, 2]
    float* out = (float*)d_out;                    // [B,T,N] = [4096][2048]

    __half *p_xa3, *p_xb3, *p_wt, *p_y, *p_wT, *p_xT;
    signed char* p_nm8;
    unsigned short* p_common16;
    cudaGetSymbolAddress((void**)&p_xa3,      g_xa3);
    cudaGetSymbolAddress((void**)&p_xb3,      g_xb3);
    cudaGetSymbolAddress((void**)&p_nm8,      g_nm8);
    cudaGetSymbolAddress((void**)&p_wt,       g_WT);
    cudaGetSymbolAddress((void**)&p_y,        g_Y);
    cudaGetSymbolAddress((void**)&p_wT,       g_wT);
    cudaGetSymbolAddress((void**)&p_xT,       g_xT);
    cudaGetSymbolAddress((void**)&p_common16, g_common16);

    cudaFuncSetAttribute(hmma_gemm<HEPI_OUT>, cudaFuncAttributeMaxDynamicSharedMemorySize, HSMEM_BYTES);
    cudaFuncSetAttribute(hmma_gemm<HEPI_Y>,   cudaFuncAttributeMaxDynamicSharedMemorySize, HSMEM_BYTES);
    cudaFuncSetAttribute(hmma_sim,            cudaFuncAttributeMaxDynamicSharedMemorySize, HSMEM_BYTES);
    cudaFuncSetAttribute(i8gemm_common,       cudaFuncAttributeMaxDynamicSharedMemorySize, I8SMEM_BYTES);

    // persistent side stream + events for fork-join capture (host handles only)
    static cudaStream_t sB = nullptr;
    static cudaEvent_t evFork = nullptr, evX = nullptr, evJoin = nullptr;
    if (sB == nullptr) {
        cudaStreamCreateWithFlags(&sB, cudaStreamNonBlocking);
        cudaEventCreateWithFlags(&evFork, cudaEventDisableTiming);
        cudaEventCreateWithFlags(&evX,    cudaEventDisableTiming);
        cudaEventCreateWithFlags(&evJoin, cudaEventDisableTiming);
    }

    // ---- fork: weight transpose on sB ----
    cudaEventRecord(evFork, 0);
    cudaStreamWaitEvent(sB, evFork, 0);
    {
        dim3 grid(TT / 32, TT / 32); dim3 blk(32, 32);
        k_wT<<<grid, blk, 0, sB>>>(weight);
    }

    // ---- default: fused x prep ----
    {
        dim3 grid(NN / 32, TT / 32); dim3 blk(32, 32);
        k_xprep<<<grid, blk>>>(x);
    }
    cudaEventRecord(evX, 0);

    // ---- sB: Y GEMM (needs xT + wT), f32 accumulate ----
    cudaStreamWaitEvent(sB, evX, 0);
    {
        dim3 grid(NN / 128, TT / 128, BB);
        hmma_gemm<HEPI_Y><<<grid, 256, HSMEM_BYTES, sB>>>(
            p_wT, p_xT, nullptr, TT, TT, TT, NN,
            (size_t)NN * TT, TT, nullptr);
    }
    cudaEventRecord(evJoin, sB);

    // ---- adjacency chain on default stream ----
    {
        dim3 blk(32, 32);
        k_norm<<<NN / 32, blk>>>();
    }
    {
        const int NTILES = (NN / 128) * (NN / 128 + 1) / 2;   // 136
        hmma_sim<<<NTILES, 256, HSMEM_BYTES>>>(p_xa3, p_xb3, gumbel);
    }
    {
        const int NTILES = (NN / 128) * (NN / 128 + 1) / 2;   // 136
        i8gemm_common<<<NTILES, 256, I8SMEM_BYTES>>>(p_nm8, p_nm8, p_common16, NN, NN, NN, NN);
    }
    {
        const int NTILES32 = (NN / 32) * (NN / 32 + 1) / 2;   // 2080
        dim3 blk(32, 32);
        k_wnT<<<NTILES32, blk>>>();
    }

    // ---- join: out GEMM needs g_Y (sB) + g_WT (default) ----
    cudaStreamWaitEvent(0, evJoin, 0);

    // out = Y @ Wn + bias  (single-term fp16, f32 accumulate, K=2048)
    {
        dim3 grid(NN / 128, (BB * TT) / 128);
        hmma_gemm<HEPI_OUT><<<grid, 256, HSMEM_BYTES>>>(
            p_y, p_wt, out, NN, NN, NN, NN, 0, 0, bias);
    }
}